// round 12
// baseline (speedup 1.0000x reference)
#include <cuda_runtime.h>
#include <cuda_bf16.h>
#include <cuda_fp16.h>
#include <cstdint>

#define BB 16
#define LL 1024
#define FF 512
#define HH 8
#define DD 64

__device__ float g_q[BB*HH*LL*DD];
__device__ float g_kT[BB*HH*DD*LL];   // K transposed: [b][h][d][l]
__device__ float g_v[BB*HH*LL*DD];
__device__ float g_x[BB*LL*HH*DD];

// ===========================================================================
// mma.sync helpers
// ===========================================================================
__device__ __forceinline__ uint32_t s2u(const void* p) {
    return (uint32_t)__cvta_generic_to_shared(p);
}
__device__ __forceinline__ void ldsm4(uint32_t* r, uint32_t a) {
    asm volatile("ldmatrix.sync.aligned.m8n8.x4.shared.b16 {%0,%1,%2,%3}, [%4];"
                 : "=r"(r[0]), "=r"(r[1]), "=r"(r[2]), "=r"(r[3]) : "r"(a));
}
__device__ __forceinline__ void ldsm4t(uint32_t* r, uint32_t a) {
    asm volatile("ldmatrix.sync.aligned.m8n8.x4.trans.shared.b16 {%0,%1,%2,%3}, [%4];"
                 : "=r"(r[0]), "=r"(r[1]), "=r"(r[2]), "=r"(r[3]) : "r"(a));
}
__device__ __forceinline__ void mma_bf16(float* c, const uint32_t* a, const uint32_t* b) {
    asm volatile(
        "mma.sync.aligned.m16n8k16.row.col.f32.bf16.bf16.f32 "
        "{%0,%1,%2,%3}, {%4,%5,%6,%7}, {%8,%9}, {%0,%1,%2,%3};"
        : "+f"(c[0]), "+f"(c[1]), "+f"(c[2]), "+f"(c[3])
        : "r"(a[0]), "r"(a[1]), "r"(a[2]), "r"(a[3]), "r"(b[0]), "r"(b[1]));
}
__device__ __forceinline__ void mma_f16(float* c, const uint32_t* a, const uint32_t* b) {
    asm volatile(
        "mma.sync.aligned.m16n8k16.row.col.f32.f16.f16.f32 "
        "{%0,%1,%2,%3}, {%4,%5,%6,%7}, {%8,%9}, {%0,%1,%2,%3};"
        : "+f"(c[0]), "+f"(c[1]), "+f"(c[2]), "+f"(c[3])
        : "r"(a[0]), "r"(a[1]), "r"(a[2]), "r"(a[3]), "r"(b[0]), "r"(b[1]));
}
__device__ __forceinline__ uint32_t packbf(float a, float b) {
    uint32_t r;
    asm("cvt.rn.bf16x2.f32 %0, %1, %2;" : "=r"(r) : "f"(b), "f"(a));
    return r;
}
__device__ __forceinline__ uint32_t packhf(float a, float b) {
    __half2 h = __floats2half2_rn(a, b);
    return *(uint32_t*)&h;
}

// ===========================================================================
// Tensor-core split-bf16 GEMM with register prefetch: C = A @ W + bias
// ===========================================================================
#define SA 40
#define SB 136

__global__ void __launch_bounds__(256) gemm_mma(
    const float* __restrict__ A, const float* __restrict__ W,
    const float* __restrict__ bias, float* __restrict__ C, int mode)
{
    __shared__ uint32_t AhU[128 * SA / 2], AlU[128 * SA / 2];
    __shared__ uint32_t BhU[32 * SB / 2],  BlU[32 * SB / 2];

    const int t    = threadIdx.x;
    const int warp = t >> 5;
    const int lane = t & 31;
    const int bm   = blockIdx.y * 128;
    const int bn   = blockIdx.x * 128;
    const int wm   = (warp >> 2) * 64;
    const int wn   = (warp & 3) * 32;

    // per-thread load coordinates
    const int am = (256 * 0 + t) >> 3;            // A rows handled: am + ch*32
    const int ak = ((t & 7) * 4);
    const int bk = t >> 5;                        // B k-rows: bk + ch*8
    const int bn2 = (t & 31) * 4;

    float acc[4][4][4];
    #pragma unroll
    for (int mt = 0; mt < 4; mt++)
        #pragma unroll
        for (int nt = 0; nt < 4; nt++)
            #pragma unroll
            for (int i = 0; i < 4; i++) acc[mt][nt][i] = 0.f;

    float4 av[4], wv[4];
    // preload chunk 0
    #pragma unroll
    for (int ch = 0; ch < 4; ch++)
        av[ch] = *(const float4*)(A + (size_t)(bm + am + ch * 32) * 512 + ak);
    #pragma unroll
    for (int ch = 0; ch < 4; ch++)
        wv[ch] = *(const float4*)(W + (size_t)(bk + ch * 8) * 512 + bn + bn2);

    for (int c = 0; c < 16; c++) {
        __syncthreads();
        // convert + store current chunk
        #pragma unroll
        for (int ch = 0; ch < 4; ch++) {
            float4 v = av[ch];
            uint32_t h0 = packbf(v.x, v.y), h1 = packbf(v.z, v.w);
            float rx = v.x - __uint_as_float(h0 << 16);
            float ry = v.y - __uint_as_float(h0 & 0xFFFF0000u);
            float rz = v.z - __uint_as_float(h1 << 16);
            float rw = v.w - __uint_as_float(h1 & 0xFFFF0000u);
            int o = (am + ch * 32) * (SA / 2) + (ak >> 1);
            AhU[o] = h0; AhU[o + 1] = h1;
            AlU[o] = packbf(rx, ry); AlU[o + 1] = packbf(rz, rw);
        }
        #pragma unroll
        for (int ch = 0; ch < 4; ch++) {
            float4 v = wv[ch];
            uint32_t h0 = packbf(v.x, v.y), h1 = packbf(v.z, v.w);
            float rx = v.x - __uint_as_float(h0 << 16);
            float ry = v.y - __uint_as_float(h0 & 0xFFFF0000u);
            float rz = v.z - __uint_as_float(h1 << 16);
            float rw = v.w - __uint_as_float(h1 & 0xFFFF0000u);
            int o = (bk + ch * 8) * (SB / 2) + (bn2 >> 1);
            BhU[o] = h0; BhU[o + 1] = h1;
            BlU[o] = packbf(rx, ry); BlU[o + 1] = packbf(rz, rw);
        }
        __syncthreads();

        // prefetch next chunk (LDG latency overlaps compute below)
        if (c + 1 < 16) {
            const int k0 = (c + 1) * 32;
            #pragma unroll
            for (int ch = 0; ch < 4; ch++)
                av[ch] = *(const float4*)(A + (size_t)(bm + am + ch * 32) * 512 + k0 + ak);
            #pragma unroll
            for (int ch = 0; ch < 4; ch++)
                wv[ch] = *(const float4*)(W + (size_t)(k0 + bk + ch * 8) * 512 + bn + bn2);
        }

        #pragma unroll
        for (int ks = 0; ks < 2; ks++) {
            const int kk = ks * 16;
            uint32_t ah[4][4], al[4][4];
            {
                int arow = (lane & 15);
                int acol = kk + ((lane >> 4) << 3);
                #pragma unroll
                for (int mt = 0; mt < 4; mt++) {
                    int boff = ((wm + mt * 16 + arow) * SA + acol) * 2;
                    ldsm4(ah[mt], s2u((const char*)AhU + boff));
                    ldsm4(al[mt], s2u((const char*)AlU + boff));
                }
            }
            uint32_t bh[4][2], bl[4][2];
            {
                int brow = kk + (lane & 15);
                int bcol = ((lane >> 4) << 3);
                #pragma unroll
                for (int ntp = 0; ntp < 2; ntp++) {
                    int boff = (brow * SB + wn + ntp * 16 + bcol) * 2;
                    uint32_t tmp[4];
                    ldsm4t(tmp, s2u((const char*)BhU + boff));
                    bh[ntp * 2][0] = tmp[0]; bh[ntp * 2][1] = tmp[1];
                    bh[ntp * 2 + 1][0] = tmp[2]; bh[ntp * 2 + 1][1] = tmp[3];
                    ldsm4t(tmp, s2u((const char*)BlU + boff));
                    bl[ntp * 2][0] = tmp[0]; bl[ntp * 2][1] = tmp[1];
                    bl[ntp * 2 + 1][0] = tmp[2]; bl[ntp * 2 + 1][1] = tmp[3];
                }
            }
            #pragma unroll
            for (int mt = 0; mt < 4; mt++)
                #pragma unroll
                for (int nt = 0; nt < 4; nt++) {
                    mma_bf16(acc[mt][nt], ah[mt], bh[nt]);
                    mma_bf16(acc[mt][nt], ah[mt], bl[nt]);
                    mma_bf16(acc[mt][nt], al[mt], bh[nt]);
                }
        }
    }

    const int lr = lane >> 2;
    const int lc = (lane & 3) * 2;

    #pragma unroll
    for (int mt = 0; mt < 4; mt++) {
        int r0 = bm + wm + mt * 16 + lr;
        #pragma unroll
        for (int nt = 0; nt < 4; nt++) {
            int col = bn + wn + nt * 8 + lc;
            float b0v = bias[col], b1v = bias[col + 1];
            float* a = acc[mt][nt];
            if (mode == 0) {
                *(float2*)&C[(size_t)r0 * 512 + col] = make_float2(a[0] + b0v, a[1] + b1v);
                *(float2*)&C[(size_t)(r0 + 8) * 512 + col] = make_float2(a[2] + b0v, a[3] + b1v);
            } else if (mode == 1) {
                int h_ = col >> 6, d_ = col & 63;
                #pragma unroll
                for (int rr = 0; rr < 2; rr++) {
                    int r = r0 + rr * 8;
                    int b_ = r >> 10, l_ = r & 1023;
                    *(float2*)&C[(((size_t)(b_ * HH + h_)) * LL + l_) * DD + d_] =
                        make_float2(a[rr * 2] + b0v, a[rr * 2 + 1] + b1v);
                }
            } else {
                int h_ = col >> 6, d_ = col & 63;
                #pragma unroll
                for (int rr = 0; rr < 2; rr++) {
                    int r = r0 + rr * 8;
                    int b_ = r >> 10, l_ = r & 1023;
                    size_t base = (((size_t)(b_ * HH + h_)) * DD + d_) * LL + l_;
                    C[base]      = a[rr * 2]     + b0v;
                    C[base + LL] = a[rr * 2 + 1] + b1v;
                }
            }
        }
    }
}

// ===========================================================================
// Flash attention on HMMA (R11 exact): QK 2-pass, PV fp16 1-pass, no-max
// softmax, deferred l-reduce.
// ===========================================================================
#define QST 72
#define KST 136
#define VST 72

__global__ void __launch_bounds__(256, 1) attn_mma(
    const float* __restrict__ q, const float* __restrict__ kT,
    const float* __restrict__ v, const float* __restrict__ toep,
    float* __restrict__ x)
{
    extern __shared__ char smc[];
    uint32_t* QhU = (uint32_t*)smc;
    uint32_t* QlU = QhU + 128 * QST / 2;
    uint32_t* KhU = QlU + 128 * QST / 2;
    uint32_t* VhU = KhU + 64 * KST / 2;
    float*    Tp  = (float*)(VhU + 128 * VST / 2);

    const int t    = threadIdx.x;
    const int warp = t >> 5;
    const int lane = t & 31;
    const int lr   = lane >> 2;
    const int lc   = (lane & 3) * 2;
    const int qt   = blockIdx.x;
    const int h    = blockIdx.y;
    const int b    = blockIdx.z;
    const int bh   = b * HH + h;

    const float* qb = q  + (size_t)bh * LL * DD + (size_t)qt * 128 * DD;
    const float* kb = kT + (size_t)bh * DD * LL;
    const float* vb = v  + (size_t)bh * LL * DD;

    #pragma unroll
    for (int ch = 0; ch < 8; ch++) {
        int fi = ch * 256 + t;
        int row = fi >> 4, dc = (fi & 15) * 4;
        float4 vv = *(const float4*)(qb + (size_t)row * 64 + dc);
        uint32_t h0 = packbf(vv.x, vv.y), h1 = packbf(vv.z, vv.w);
        float rx = vv.x - __uint_as_float(h0 << 16);
        float ry = vv.y - __uint_as_float(h0 & 0xFFFF0000u);
        float rz = vv.z - __uint_as_float(h1 << 16);
        float rw = vv.w - __uint_as_float(h1 & 0xFFFF0000u);
        int o = row * (QST / 2) + (dc >> 1);
        QhU[o] = h0; QhU[o + 1] = h1;
        QlU[o] = packbf(rx, ry); QlU[o + 1] = packbf(rz, rw);
    }
    {
        const float4* tg = (const float4*)(toep + (size_t)h * 4096);
        #pragma unroll
        for (int ch = 0; ch < 4; ch++) {
            int fi = ch * 256 + t;
            *(float4*)&Tp[fi * 4] = tg[fi];
        }
    }

    int qg0 = qt * 128 + warp * 16 + lr;
    int qg1 = qg0 + 8;
    const int qo0 = ((qg0 >> 5) << 6) + (qg0 & 31) + 2080;
    const int qo1 = ((qg1 >> 5) << 6) + (qg1 & 31) + 2080;

    float l0 = 0.f, l1 = 0.f;
    float O[8][4];
    #pragma unroll
    for (int nf = 0; nf < 8; nf++)
        #pragma unroll
        for (int i = 0; i < 4; i++) O[nf][i] = 0.f;

    const float scale = 0.125f;

    for (int kt = 0; kt < 8; kt++) {
        #pragma unroll
        for (int ch = 0; ch < 8; ch++) {
            int fi = ch * 256 + t;
            int d = fi >> 5, kc = (fi & 31) * 4;
            float4 vv = *(const float4*)(kb + (size_t)d * LL + kt * 128 + kc);
            int o = d * (KST / 2) + (kc >> 1);
            KhU[o] = packbf(vv.x, vv.y);
            KhU[o + 1] = packbf(vv.z, vv.w);
        }
        #pragma unroll
        for (int ch = 0; ch < 8; ch++) {
            int fi = ch * 256 + t;
            int key = fi >> 4, dc = (fi & 15) * 4;
            float4 vv = *(const float4*)(vb + (size_t)(kt * 128 + key) * 64 + dc);
            int o = key * (VST / 2) + (dc >> 1);
            VhU[o] = packhf(vv.x, vv.y);
            VhU[o + 1] = packhf(vv.z, vv.w);
        }
        __syncthreads();

        // ---- S = Q K^T (2 passes: q_hi*k + q_lo*k) ----
        float S[16][4];
        #pragma unroll
        for (int nf = 0; nf < 16; nf++)
            #pragma unroll
            for (int i = 0; i < 4; i++) S[nf][i] = 0.f;

        #pragma unroll
        for (int ks = 0; ks < 4; ks++) {
            uint32_t ah[4], al[4];
            int arow = warp * 16 + (lane & 15);
            int acol = ks * 16 + ((lane >> 4) << 3);
            ldsm4(ah, s2u((const char*)QhU + (arow * QST + acol) * 2));
            ldsm4(al, s2u((const char*)QlU + (arow * QST + acol) * 2));
            int brow = ks * 16 + (lane & 15);
            int bcol = (lane >> 4) << 3;
            #pragma unroll
            for (int nf2 = 0; nf2 < 8; nf2++) {
                uint32_t bhv[4];
                ldsm4t(bhv, s2u((const char*)KhU + (brow * KST + nf2 * 16 + bcol) * 2));
                mma_bf16(S[nf2 * 2],     ah, bhv);
                mma_bf16(S[nf2 * 2],     al, bhv);
                mma_bf16(S[nf2 * 2 + 1], ah, bhv + 2);
                mma_bf16(S[nf2 * 2 + 1], al, bhv + 2);
            }
        }

        // ---- scale + bias + exp ----
        uint32_t ph[16][2];
        float sum0 = 0.f, sum1 = 0.f;
        #pragma unroll
        for (int nf = 0; nf < 16; nf++) {
            int kg0 = kt * 128 + nf * 8 + lc;
            int ko0 = ((kg0 >> 5) << 6) + (kg0 & 31);
            int kg1 = kg0 + 1;
            int ko1 = ((kg1 >> 5) << 6) + (kg1 & 31);
            float e0 = __expf(S[nf][0] * scale + Tp[qo0 - ko0]);
            float e1 = __expf(S[nf][1] * scale + Tp[qo0 - ko1]);
            float e2 = __expf(S[nf][2] * scale + Tp[qo1 - ko0]);
            float e3 = __expf(S[nf][3] * scale + Tp[qo1 - ko1]);
            sum0 += e0 + e1;
            sum1 += e2 + e3;
            ph[nf][0] = packhf(e0, e1);
            ph[nf][1] = packhf(e2, e3);
        }
        l0 += sum0;
        l1 += sum1;

        // ---- O += P V (fp16, single pass) ----
        #pragma unroll
        for (int ks = 0; ks < 8; ks++) {
            uint32_t pa[4] = { ph[ks * 2][0], ph[ks * 2][1],
                               ph[ks * 2 + 1][0], ph[ks * 2 + 1][1] };
            int brow = ks * 16 + (lane & 15);
            int bcol = (lane >> 4) << 3;
            #pragma unroll
            for (int nf2 = 0; nf2 < 4; nf2++) {
                uint32_t bhv[4];
                ldsm4t(bhv, s2u((const char*)VhU + (brow * VST + nf2 * 16 + bcol) * 2));
                mma_f16(O[nf2 * 2],     pa, bhv);
                mma_f16(O[nf2 * 2 + 1], pa, bhv + 2);
            }
        }
        __syncthreads();
    }

    l0 += __shfl_xor_sync(0xffffffffu, l0, 1);
    l0 += __shfl_xor_sync(0xffffffffu, l0, 2);
    l1 += __shfl_xor_sync(0xffffffffu, l1, 1);
    l1 += __shfl_xor_sync(0xffffffffu, l1, 2);

    float inv0 = 1.0f / l0, inv1 = 1.0f / l1;
    int row0 = b * LL + qt * 128 + warp * 16 + lr;
    #pragma unroll
    for (int nf = 0; nf < 8; nf++) {
        int col = h * 64 + nf * 8 + lc;
        *(float2*)&x[(size_t)row0 * 512 + col] =
            make_float2(O[nf][0] * inv0, O[nf][1] * inv0);
        *(float2*)&x[(size_t)(row0 + 8) * 512 + col] =
            make_float2(O[nf][2] * inv1, O[nf][3] * inv1);
    }
}

// ===========================================================================
extern "C" void kernel_launch(void* const* d_in, const int* in_sizes, int n_in,
                              void* d_out, int out_size)
{
    const float* inq  = (const float*)d_in[0];
    const float* inkv = (const float*)d_in[1];
    const float* Wq   = (const float*)d_in[2];
    const float* bq   = (const float*)d_in[3];
    const float* Wk   = (const float*)d_in[4];
    const float* bk   = (const float*)d_in[5];
    const float* Wv   = (const float*)d_in[6];
    const float* bv   = (const float*)d_in[7];
    const float* Wo   = (const float*)d_in[8];
    const float* bo   = (const float*)d_in[9];
    const float* toep = (const float*)d_in[10];
    float* out = (float*)d_out;

    float *pq, *pkT, *pv, *px;
    cudaGetSymbolAddress((void**)&pq,  g_q);
    cudaGetSymbolAddress((void**)&pkT, g_kT);
    cudaGetSymbolAddress((void**)&pv,  g_v);
    cudaGetSymbolAddress((void**)&px,  g_x);

    dim3 gg(4, 128);

    gemm_mma<<<gg, 256>>>(inq,  Wq, bq, pq,  1);
    gemm_mma<<<gg, 256>>>(inkv, Wk, bk, pkT, 2);
    gemm_mma<<<gg, 256>>>(inkv, Wv, bv, pv,  1);

    int smem = 2 * (128 * QST * 2) + (64 * KST * 2) + (128 * VST * 2) + 4096 * 4;
    cudaFuncSetAttribute(attn_mma, cudaFuncAttributeMaxDynamicSharedMemorySize, smem);
    attn_mma<<<dim3(8, HH, BB), 256, smem>>>(pq, pkT, pv, toep, px);

    gemm_mma<<<gg, 256>>>(px, Wo, bo, out, 0);
}